// round 12
// baseline (speedup 1.0000x reference)
#include <cuda_runtime.h>
#include <cuda_fp16.h>
#include <math_constants.h>
#include <cstdint>

#define BATCH 8192
#define DIM   128
#define BM    128
#define BN    128
#define MARGIN_F 0.5f

#define MTILES 64
#define NPAIRS_SYM 2080                  // 64*65/2 upper-triangular tile pairs
#define GRID_G 148                       // persistent, 1 CTA/SM
#define NTHREADS 1024                    // 32 warps: 4 (M) x 8 (N), warp tile 32x16

#define ROWP 272                         // smem pitch: 256B data + 16B pad (conflict-free LDSM)
#define TILE_SZ (128 * ROWP)             // 34816
#define SM_A    0
#define SM_B0   (TILE_SZ)                // 34816
#define SM_B1   (2 * TILE_SZ)            // 69632
#define SM_NRM0 (3 * TILE_SZ)            // 104448
#define SM_LBL0 (SM_NRM0 + 512)
#define SM_NRM1 (SM_LBL0 + 512)
#define SM_LBL1 (SM_NRM1 + 512)
#define SM_CMAX (SM_LBL1 + 512)          // [4][128] float per-mwarp col max
#define SM_CMIN (SM_CMAX + 2048)         // [4][128] float per-mwarp col min
#define SM_TOTAL (SM_CMIN + 2048)        // 110592

// ---- scratch (no allocations allowed) ----
__device__ float  g_norms[BATCH];
__device__ int    g_maxpos[BATCH];       // d^2 float bits (clamped >=0: int order == float order)
__device__ int    g_minneg[BATCH];
__device__ __half g_sp[BATCH * 128];     // fp16 embeddings, row-major

// ================= helpers =================
__device__ __forceinline__ uint32_t smem_u32(const void* p) {
    uint32_t a;
    asm("{ .reg .u64 t; cvta.to.shared.u64 t, %1; cvt.u32.u64 %0, t; }" : "=r"(a) : "l"(p));
    return a;
}
__device__ __forceinline__ void cp16(uint32_t dst, const void* src) {
    asm volatile("cp.async.cg.shared.global [%0], [%1], 16;" :: "r"(dst), "l"(src));
}
#define CP_COMMIT() asm volatile("cp.async.commit_group;" ::: "memory")
#define CP_WAIT(n)  asm volatile("cp.async.wait_group %0;" :: "n"(n) : "memory")

#define LDSM4(r, addr) \
    asm volatile("ldmatrix.sync.aligned.m8n8.x4.shared.b16 {%0,%1,%2,%3}, [%4];" \
                 : "=r"((r)[0]), "=r"((r)[1]), "=r"((r)[2]), "=r"((r)[3]) : "r"(addr))

#define MMAF16(d, a, b) \
    asm volatile("mma.sync.aligned.m16n8k16.row.col.f32.f16.f16.f32 " \
                 "{%0,%1,%2,%3}, {%4,%5,%6,%7}, {%8,%9}, {%0,%1,%2,%3};" \
                 : "+f"((d)[0]), "+f"((d)[1]), "+f"((d)[2]), "+f"((d)[3]) \
                 : "r"((a)[0]), "r"((a)[1]), "r"((a)[2]), "r"((a)[3]), \
                   "r"((b)[0]), "r"((b)[1]))

// ---- kernel 1: norms + fp16 cast + init accumulators ----
__global__ void prep_kernel(const float* __restrict__ emb) {
    int row  = blockIdx.x * 8 + (threadIdx.x >> 5);
    int lane = threadIdx.x & 31;
    float4 v = reinterpret_cast<const float4*>(emb)[row * 32 + lane];
    float s = v.x * v.x + v.y * v.y + v.z * v.z + v.w * v.w;
    #pragma unroll
    for (int o = 16; o; o >>= 1) s += __shfl_xor_sync(0xffffffffu, s, o);
    if (lane == 0) {
        g_norms[row]  = s;
        g_maxpos[row] = 0xFF800000;  // -inf bits
        g_minneg[row] = 0x7F800000;  // +inf bits
    }
    __half2* dst = reinterpret_cast<__half2*>(g_sp + (size_t)row * 128);
    dst[lane * 2 + 0] = __half2(__float2half_rn(v.x), __float2half_rn(v.y));
    dst[lane * 2 + 1] = __half2(__float2half_rn(v.z), __float2half_rn(v.w));
}

// async-copy one [128 x 256B] fp16 tile into pitch-272 smem
__device__ __forceinline__ void load_tile_async(const char* __restrict__ src,
                                                uint32_t sdst, int tid) {
    #pragma unroll
    for (int i = tid; i < 2048; i += NTHREADS) {
        int row = i >> 4, ch = i & 15;
        cp16(sdst + row * ROWP + ch * 16, src + row * 256 + ch * 16);
    }
}

// ---- kernel 2: persistent symmetric fp16 GEMM + fused hardest-pos/neg (d^2), 32 warps ----
__global__ __launch_bounds__(NTHREADS, 1)
void dist_kernel(const int* __restrict__ labels) {
    extern __shared__ char smem[];
    const uint32_t sbase = smem_u32(smem);
    const int tid   = threadIdx.x;
    const int warp  = tid >> 5;
    const int lane  = tid & 31;
    const int mwarp = warp & 3;          // 4 warps over M (32 rows each)
    const int nwarp = warp >> 2;         // 8 warps over N (16 cols each)

    float* nrmS[2] = { (float*)(smem + SM_NRM0), (float*)(smem + SM_NRM1) };
    int*   lblS[2] = { (int*)  (smem + SM_LBL0), (int*)  (smem + SM_LBL1) };
    float* credMax = (float*)(smem + SM_CMAX);   // [4][128] (indexed by mwarp)
    float* credMin = (float*)(smem + SM_CMIN);   // [4][128]
    const uint32_t sBO[2] = { sbase + SM_B0, sbase + SM_B1 };

    // per-thread ldmatrix base offsets
    const uint32_t aBase = sbase + SM_A +
        (uint32_t)(mwarp * 32 + (lane & 15)) * ROWP + ((lane >> 4) * 16);
    const uint32_t bRow  =
        (uint32_t)(nwarp * 16 + (lane & 7) + ((lane >> 4) & 1) * 8) * ROWP +
        (((lane >> 3) & 1) * 16);

    int p  = (int)(((long long)blockIdx.x       * NPAIRS_SYM) / GRID_G);
    int p1 = (int)(((long long)(blockIdx.x + 1) * NPAIRS_SYM) / GRID_G);

    int mt = 0, S = 0;                   // row decode: row mt starts at linear index S
    while (S + (MTILES - mt) <= p) { S += MTILES - mt; mt++; }

    while (p < p1) {
        const int rowEnd = S + (MTILES - mt);
        const int pend   = min(p1, rowEnd);
        const int m0     = mt * BM;

        __syncthreads();  // previous range fully done with all smem buffers

        float nrmA[4]; int lblA[4], mrowA[4];
        #pragma unroll
        for (int i = 0; i < 4; i++) {
            int rl = mwarp * 32 + ((i >> 1) * 16) + ((i & 1) * 8) + (lane >> 2);
            mrowA[i] = m0 + rl;
            nrmA[i]  = g_norms[mrowA[i]];
            lblA[i]  = labels[mrowA[i]];
        }
        float maxpos[4], minneg[4];
        #pragma unroll
        for (int i = 0; i < 4; i++) { maxpos[i] = -CUDART_INF_F; minneg[i] = CUDART_INF_F; }

        // prologue: A + B(first) in one cp.async group
        load_tile_async((const char*)(g_sp + (size_t)m0 * 128), sbase + SM_A, tid);
        {
            const int n0 = (mt + (p - S)) * BN;
            load_tile_async((const char*)(g_sp + (size_t)n0 * 128), sBO[0], tid);
            if (tid < BN) { nrmS[0][tid] = g_norms[n0 + tid]; lblS[0][tid] = labels[n0 + tid]; }
        }
        CP_COMMIT();

        int cur = 0;
        for (int j = p; j < pend; j++) {
            const int ntile = mt + (j - S);
            const int n0    = ntile * BN;
            const bool offd = (ntile != mt);
            const bool have_next = (j + 1 < pend);
            if (have_next) {
                const int n0n = (ntile + 1) * BN;
                load_tile_async((const char*)(g_sp + (size_t)n0n * 128), sBO[cur ^ 1], tid);
                if (tid < BN) {
                    nrmS[cur ^ 1][tid] = g_norms[n0n + tid];
                    lblS[cur ^ 1][tid] = labels[n0n + tid];
                }
                CP_COMMIT();
                CP_WAIT(1);
            } else {
                CP_WAIT(0);
            }
            __syncthreads();      // B(j) (and A) visible

            // ---- 1-pass fp16 GEMM on 32x16 warp tile ----
            float acc[2][2][4];
            #pragma unroll
            for (int a = 0; a < 2; a++)
                #pragma unroll
                for (int b = 0; b < 2; b++)
                    #pragma unroll
                    for (int c = 0; c < 4; c++) acc[a][b][c] = 0.f;

            const uint32_t bBase = sBO[cur] + bRow;
            #pragma unroll
            for (int ks = 0; ks < 8; ks++) {
                uint32_t a0[4], a1[4], b[4];
                LDSM4(a0, aBase + ks * 32);
                LDSM4(a1, aBase + ks * 32 + 16 * ROWP);
                LDSM4(b, bBase + ks * 32);
                #pragma unroll
                for (int nt = 0; nt < 2; nt++) {
                    uint32_t* bp = &b[nt * 2];
                    MMAF16(acc[0][nt], a0, bp);
                    MMAF16(acc[1][nt], a1, bp);
                }
            }

            // ---- fused epilogue in d^2 space: row-side always, col-side if off-diagonal ----
            float cmax[4], cmin[4];
            #pragma unroll
            for (int k = 0; k < 4; k++) { cmax[k] = -CUDART_INF_F; cmin[k] = CUDART_INF_F; }
            {
                const float* nB = nrmS[cur];
                const int*   lB = lblS[cur];
                #pragma unroll
                for (int mtl = 0; mtl < 2; mtl++)
                    #pragma unroll
                    for (int half = 0; half < 2; half++) {
                        const int i   = mtl * 2 + half;
                        const float nA = nrmA[i];
                        const int   lA = lblA[i];
                        const int   mr = mrowA[i];
                        #pragma unroll
                        for (int nt = 0; nt < 2; nt++) {
                            #pragma unroll
                            for (int cc = 0; cc < 2; cc++) {
                                int col = nwarp * 16 + nt * 8 + (lane & 3) * 2 + cc;
                                float dot = acc[mtl][nt][half * 2 + cc];
                                float d2  = fmaxf(fmaf(-2.f, dot, nA + nB[col]), 0.f);
                                bool same = (lA == lB[col]);
                                if (mr != n0 + col) {
                                    if (same) maxpos[i] = fmaxf(maxpos[i], d2);
                                    else      minneg[i] = fminf(minneg[i], d2);
                                }
                                if (offd) {
                                    int k = nt * 2 + cc;
                                    if (same) cmax[k] = fmaxf(cmax[k], d2);
                                    else      cmin[k] = fminf(cmin[k], d2);
                                }
                            }
                        }
                    }
            }
            if (offd) {
                // reduce columns over the 8 row-groups (lanes differing in bits 2..4)
                #pragma unroll
                for (int k = 0; k < 4; k++) {
                    #pragma unroll
                    for (int o = 4; o <= 16; o <<= 1) {
                        cmax[k] = fmaxf(cmax[k], __shfl_xor_sync(0xffffffffu, cmax[k], o));
                        cmin[k] = fminf(cmin[k], __shfl_xor_sync(0xffffffffu, cmin[k], o));
                    }
                }
                if ((lane >> 2) == 0) {
                    #pragma unroll
                    for (int k = 0; k < 4; k++) {
                        int col = nwarp * 16 + (k >> 1) * 8 + (lane & 3) * 2 + (k & 1);
                        credMax[mwarp * 128 + col] = cmax[k];
                        credMin[mwarp * 128 + col] = cmin[k];
                    }
                }
            }
            __syncthreads();      // buf[cur] reads done; colred staged
            if (offd && tid < 128) {
                float mx = fmaxf(fmaxf(credMax[tid],       credMax[128 + tid]),
                                 fmaxf(credMax[256 + tid], credMax[384 + tid]));
                float mn = fminf(fminf(credMin[tid],       credMin[128 + tid]),
                                 fminf(credMin[256 + tid], credMin[384 + tid]));
                atomicMax(&g_maxpos[n0 + tid], __float_as_int(mx));  // -inf bits = no-op
                atomicMin(&g_minneg[n0 + tid], __float_as_int(mn));  // +inf bits = no-op
            }
            if (have_next) cur ^= 1;
        }

        // row-side: reduce across the 4 lanes of each quad, then atomics
        #pragma unroll
        for (int i = 0; i < 4; i++) {
            #pragma unroll
            for (int o = 1; o <= 2; o <<= 1) {
                maxpos[i] = fmaxf(maxpos[i], __shfl_xor_sync(0xffffffffu, maxpos[i], o));
                minneg[i] = fminf(minneg[i], __shfl_xor_sync(0xffffffffu, minneg[i], o));
            }
        }
        if ((lane & 3) == 0) {
            #pragma unroll
            for (int i = 0; i < 4; i++) {
                atomicMax(&g_maxpos[mrowA[i]], __float_as_int(maxpos[i]));
                atomicMin(&g_minneg[mrowA[i]], __float_as_int(minneg[i]));
            }
        }
        p = pend;
        if (p == rowEnd) { S = rowEnd; mt++; }
    }
}

// ---- kernel 3: single-block finalize (sqrt applied here; monotone) ----
__global__ __launch_bounds__(1024)
void finalize_kernel(float* __restrict__ out) {
    __shared__ float ssum[1024], scnt[1024];
    float s = 0.f, c = 0.f;
    for (int i = threadIdx.x; i < BATCH; i += 1024) {
        int mp = g_maxpos[i], mn = g_minneg[i];
        bool valid = (mp != (int)0xFF800000) && (mn != 0x7F800000);
        float hp = sqrtf(fmaxf(__int_as_float(mp), 0.f));
        float hn = sqrtf(fmaxf(__int_as_float(mn), 0.f));
        float per = fmaxf(hp - hn + MARGIN_F, 0.f);
        if (valid) { s += per; c += 1.f; }
    }
    ssum[threadIdx.x] = s; scnt[threadIdx.x] = c;
    __syncthreads();
    for (int st = 512; st; st >>= 1) {
        if (threadIdx.x < st) {
            ssum[threadIdx.x] += ssum[threadIdx.x + st];
            scnt[threadIdx.x] += scnt[threadIdx.x + st];
        }
        __syncthreads();
    }
    if (threadIdx.x == 0) out[0] = ssum[0] / fmaxf(scnt[0], 1.f);
}

extern "C" void kernel_launch(void* const* d_in, const int* in_sizes, int n_in,
                              void* d_out, int out_size) {
    const float* emb = (const float*)d_in[0];
    const int*   lbl = (const int*)d_in[1];   // jax int64 -> int32 (no x64)
    (void)in_sizes; (void)n_in; (void)out_size;

    cudaFuncSetAttribute(dist_kernel, cudaFuncAttributeMaxDynamicSharedMemorySize, SM_TOTAL);

    prep_kernel<<<BATCH / 8, 256>>>(emb);
    dist_kernel<<<GRID_G, NTHREADS, SM_TOTAL>>>(lbl);
    finalize_kernel<<<1, 1024>>>((float*)d_out);
}

// round 13
// speedup vs baseline: 1.1977x; 1.1977x over previous
#include <cuda_runtime.h>
#include <cuda_fp16.h>
#include <math_constants.h>
#include <cstdint>

#define BATCH 8192
#define DIM   128
#define BM    128
#define BN    128
#define MARGIN_F 0.5f

#define MTILES 64
#define NPAIRS_SYM 2080                  // 64*65/2 upper-triangular tile pairs
#define GRID_G 148                       // persistent, 1 CTA/SM
#define NTHREADS 512                     // 16 warps: 4 (M) x 4 (N), warp tile 32x32

#define ROWP 272                         // smem pitch: 256B data + 16B pad (conflict-free LDSM)
#define TILE_SZ (128 * ROWP)             // 34816
#define SM_A    0
#define SM_BBUF(i) (TILE_SZ * (1 + (i))) // 3 B buffers
#define SM_META (4 * TILE_SZ)            // 139264; per buffer: nrm[128]f + lbl[128]i = 1024B
#define SM_TOTAL (SM_META + 3 * 1024)    // 142336

// ---- scratch (no allocations allowed) ----
__device__ float  g_norms[BATCH];
__device__ int    g_maxpos[BATCH];       // d^2 float bits (clamped >=0: int order == float order)
__device__ int    g_minneg[BATCH];
__device__ __half g_sp[BATCH * 128];     // fp16 embeddings, row-major

// ================= helpers =================
__device__ __forceinline__ uint32_t smem_u32(const void* p) {
    uint32_t a;
    asm("{ .reg .u64 t; cvta.to.shared.u64 t, %1; cvt.u32.u64 %0, t; }" : "=r"(a) : "l"(p));
    return a;
}
__device__ __forceinline__ void cp16(uint32_t dst, const void* src) {
    asm volatile("cp.async.cg.shared.global [%0], [%1], 16;" :: "r"(dst), "l"(src));
}
#define CP_COMMIT() asm volatile("cp.async.commit_group;" ::: "memory")
#define CP_WAIT(n)  asm volatile("cp.async.wait_group %0;" :: "n"(n) : "memory")

#define LDSM4(r, addr) \
    asm volatile("ldmatrix.sync.aligned.m8n8.x4.shared.b16 {%0,%1,%2,%3}, [%4];" \
                 : "=r"((r)[0]), "=r"((r)[1]), "=r"((r)[2]), "=r"((r)[3]) : "r"(addr))

#define MMAF16(d, a, b) \
    asm volatile("mma.sync.aligned.m16n8k16.row.col.f32.f16.f16.f32 " \
                 "{%0,%1,%2,%3}, {%4,%5,%6,%7}, {%8,%9}, {%0,%1,%2,%3};" \
                 : "+f"((d)[0]), "+f"((d)[1]), "+f"((d)[2]), "+f"((d)[3]) \
                 : "r"((a)[0]), "r"((a)[1]), "r"((a)[2]), "r"((a)[3]), \
                   "r"((b)[0]), "r"((b)[1]))

// ---- kernel 1: norms + fp16 cast + init accumulators ----
__global__ void prep_kernel(const float* __restrict__ emb) {
    int row  = blockIdx.x * 8 + (threadIdx.x >> 5);
    int lane = threadIdx.x & 31;
    float4 v = reinterpret_cast<const float4*>(emb)[row * 32 + lane];
    float s = v.x * v.x + v.y * v.y + v.z * v.z + v.w * v.w;
    #pragma unroll
    for (int o = 16; o; o >>= 1) s += __shfl_xor_sync(0xffffffffu, s, o);
    if (lane == 0) {
        g_norms[row]  = s;
        g_maxpos[row] = 0xFF800000;  // -inf bits
        g_minneg[row] = 0x7F800000;  // +inf bits
    }
    __half2* dst = reinterpret_cast<__half2*>(g_sp + (size_t)row * 128);
    dst[lane * 2 + 0] = __half2(__float2half_rn(v.x), __float2half_rn(v.y));
    dst[lane * 2 + 1] = __half2(__float2half_rn(v.z), __float2half_rn(v.w));
}

// async-copy one [128 x 256B] fp16 tile into pitch-272 smem
__device__ __forceinline__ void load_tile_async(const char* __restrict__ src,
                                                uint32_t sdst, int tid) {
    #pragma unroll
    for (int i = tid; i < 2048; i += NTHREADS) {
        int row = i >> 4, ch = i & 15;
        cp16(sdst + row * ROWP + ch * 16, src + row * 256 + ch * 16);
    }
}

// ---- kernel 2: persistent symmetric fp16 GEMM + fused hardest-pos/neg (d^2) ----
// single __syncthreads per tile: triple-buffered B + direct per-lane REDG flush
__global__ __launch_bounds__(NTHREADS, 1)
void dist_kernel(const int* __restrict__ labels) {
    extern __shared__ char smem[];
    const uint32_t sbase = smem_u32(smem);
    const int tid   = threadIdx.x;
    const int warp  = tid >> 5;
    const int lane  = tid & 31;
    const int mwarp = warp & 3;          // 4 warps over M (32 rows each)
    const int nwarp = warp >> 2;         // 4 warps over N (32 cols each)

    const uint32_t aBase = sbase + SM_A +
        (uint32_t)(mwarp * 32 + (lane & 15)) * ROWP + ((lane >> 4) * 16);
    const uint32_t bRow  =
        (uint32_t)(nwarp * 32 + (lane & 7) + ((lane >> 4) & 1) * 8) * ROWP +
        (((lane >> 3) & 1) * 16);

    int p  = (int)(((long long)blockIdx.x       * NPAIRS_SYM) / GRID_G);
    int p1 = (int)(((long long)(blockIdx.x + 1) * NPAIRS_SYM) / GRID_G);

    int mt = 0, S = 0;                   // row decode: row mt starts at linear index S
    while (S + (MTILES - mt) <= p) { S += MTILES - mt; mt++; }

    while (p < p1) {
        const int rowEnd = S + (MTILES - mt);
        const int pend   = min(p1, rowEnd);
        const int m0     = mt * BM;
        const int ncnt   = pend - p;
        const int nfirst = mt + (p - S);

        __syncthreads();  // previous m-range fully done with all smem buffers

        float nrmA[4]; int lblA[4], mrowA[4];
        #pragma unroll
        for (int i = 0; i < 4; i++) {
            int rl = mwarp * 32 + ((i >> 1) * 16) + ((i & 1) * 8) + (lane >> 2);
            mrowA[i] = m0 + rl;
            nrmA[i]  = g_norms[mrowA[i]];
            lblA[i]  = labels[mrowA[i]];
        }
        float maxpos[4], minneg[4];
        #pragma unroll
        for (int i = 0; i < 4; i++) { maxpos[i] = -CUDART_INF_F; minneg[i] = CUDART_INF_F; }

        // prologue: A + B(first) in one cp.async group (buffer 0)
        load_tile_async((const char*)(g_sp + (size_t)m0 * 128), sbase + SM_A, tid);
        {
            const int n0 = nfirst * BN;
            load_tile_async((const char*)(g_sp + (size_t)n0 * 128), sbase + SM_BBUF(0), tid);
            if (tid < BN) {
                ((float*)(smem + SM_META))[tid]       = g_norms[n0 + tid];
                ((int*)  (smem + SM_META + 512))[tid] = labels[n0 + tid];
            }
        }
        CP_COMMIT();

        for (int t = 0; t < ncnt; t++) {
            const int ntile = nfirst + t;
            const int n0    = ntile * BN;
            const bool offd = (ntile != mt);
            const int rb    = t % 3;
            if (t + 1 < ncnt) {
                const int wb  = (t + 1) % 3;
                const int n0n = (ntile + 1) * BN;
                load_tile_async((const char*)(g_sp + (size_t)n0n * 128),
                                sbase + SM_BBUF(wb), tid);
                if (tid < BN) {
                    ((float*)(smem + SM_META + wb * 1024))[tid]       = g_norms[n0n + tid];
                    ((int*)  (smem + SM_META + wb * 1024 + 512))[tid] = labels[n0n + tid];
                }
                CP_COMMIT();
                CP_WAIT(1);
            } else {
                CP_WAIT(0);
            }
            __syncthreads();      // single barrier per tile: buf[rb] + meta visible

            // ---- 1-pass fp16 GEMM on 32x32 warp tile ----
            float acc[2][4][4];
            #pragma unroll
            for (int a = 0; a < 2; a++)
                #pragma unroll
                for (int b = 0; b < 4; b++)
                    #pragma unroll
                    for (int c = 0; c < 4; c++) acc[a][b][c] = 0.f;

            const uint32_t bBase = sbase + SM_BBUF(rb) + bRow;
            #pragma unroll
            for (int ks = 0; ks < 8; ks++) {
                uint32_t a0[4], a1[4], b[2][4];
                LDSM4(a0, aBase + ks * 32);
                LDSM4(a1, aBase + ks * 32 + 16 * ROWP);
                #pragma unroll
                for (int np = 0; np < 2; np++)
                    LDSM4(b[np], bBase + (uint32_t)(np * 16) * ROWP + ks * 32);
                #pragma unroll
                for (int nt = 0; nt < 4; nt++) {
                    uint32_t* bp = &b[nt >> 1][(nt & 1) * 2];
                    MMAF16(acc[0][nt], a0, bp);
                    MMAF16(acc[1][nt], a1, bp);
                }
            }

            // ---- fused epilogue in d^2 space ----
            const float* nB = (const float*)(smem + SM_META + rb * 1024);
            const int*   lB = (const int*)  (smem + SM_META + rb * 1024 + 512);
            float cmax[8], cmin[8];
            #pragma unroll
            for (int k = 0; k < 8; k++) { cmax[k] = -CUDART_INF_F; cmin[k] = CUDART_INF_F; }
            #pragma unroll
            for (int mtl = 0; mtl < 2; mtl++)
                #pragma unroll
                for (int half = 0; half < 2; half++) {
                    const int i   = mtl * 2 + half;
                    const float nA = nrmA[i];
                    const int   lA = lblA[i];
                    const int   mr = mrowA[i];
                    #pragma unroll
                    for (int nt = 0; nt < 4; nt++) {
                        #pragma unroll
                        for (int cc = 0; cc < 2; cc++) {
                            int col = nwarp * 32 + nt * 8 + (lane & 3) * 2 + cc;
                            float dot = acc[mtl][nt][half * 2 + cc];
                            float d2  = fmaxf(fmaf(-2.f, dot, nA + nB[col]), 0.f);
                            bool same = (lA == lB[col]);
                            if (mr != n0 + col) {
                                if (same) maxpos[i] = fmaxf(maxpos[i], d2);
                                else      minneg[i] = fminf(minneg[i], d2);
                            }
                            if (offd) {
                                int k = nt * 2 + cc;
                                if (same) cmax[k] = fmaxf(cmax[k], d2);
                                else      cmin[k] = fminf(cmin[k], d2);
                            }
                        }
                    }
                }
            if (offd) {
                // reduce columns over the 8 row-groups (lanes differing in bits 2..4)
                #pragma unroll
                for (int k = 0; k < 8; k++) {
                    #pragma unroll
                    for (int o = 4; o <= 16; o <<= 1) {
                        cmax[k] = fmaxf(cmax[k], __shfl_xor_sync(0xffffffffu, cmax[k], o));
                        cmin[k] = fminf(cmin[k], __shfl_xor_sync(0xffffffffu, cmin[k], o));
                    }
                }
                // each lane flushes one column: digit g = lane>>2, quad q = lane&3
                const int g = lane >> 2, q = lane & 3;
                float vmax = cmax[0], vmin = cmin[0];
                #pragma unroll
                for (int k = 1; k < 8; k++) {
                    if (g == k) { vmax = cmax[k]; vmin = cmin[k]; }
                }
                const int col = nwarp * 32 + ((g >> 1) * 8) + q * 2 + (g & 1);
                atomicMax(&g_maxpos[n0 + col], __float_as_int(vmax));  // -inf bits = no-op
                atomicMin(&g_minneg[n0 + col], __float_as_int(vmin));  // +inf bits = no-op
            }
        }

        // row-side: reduce across the 4 lanes of each quad, then atomics
        #pragma unroll
        for (int i = 0; i < 4; i++) {
            #pragma unroll
            for (int o = 1; o <= 2; o <<= 1) {
                maxpos[i] = fmaxf(maxpos[i], __shfl_xor_sync(0xffffffffu, maxpos[i], o));
                minneg[i] = fminf(minneg[i], __shfl_xor_sync(0xffffffffu, minneg[i], o));
            }
        }
        if ((lane & 3) == 0) {
            #pragma unroll
            for (int i = 0; i < 4; i++) {
                atomicMax(&g_maxpos[mrowA[i]], __float_as_int(maxpos[i]));
                atomicMin(&g_minneg[mrowA[i]], __float_as_int(minneg[i]));
            }
        }
        p = pend;
        if (p == rowEnd) { S = rowEnd; mt++; }
    }
}

// ---- kernel 3: single-block finalize (sqrt applied here; monotone) ----
__global__ __launch_bounds__(1024)
void finalize_kernel(float* __restrict__ out) {
    __shared__ float ssum[1024], scnt[1024];
    float s = 0.f, c = 0.f;
    for (int i = threadIdx.x; i < BATCH; i += 1024) {
        int mp = g_maxpos[i], mn = g_minneg[i];
        bool valid = (mp != (int)0xFF800000) && (mn != 0x7F800000);
        float hp = sqrtf(fmaxf(__int_as_float(mp), 0.f));
        float hn = sqrtf(fmaxf(__int_as_float(mn), 0.f));
        float per = fmaxf(hp - hn + MARGIN_F, 0.f);
        if (valid) { s += per; c += 1.f; }
    }
    ssum[threadIdx.x] = s; scnt[threadIdx.x] = c;
    __syncthreads();
    for (int st = 512; st; st >>= 1) {
        if (threadIdx.x < st) {
            ssum[threadIdx.x] += ssum[threadIdx.x + st];
            scnt[threadIdx.x] += scnt[threadIdx.x + st];
        }
        __syncthreads();
    }
    if (threadIdx.x == 0) out[0] = ssum[0] / fmaxf(scnt[0], 1.f);
}

extern "C" void kernel_launch(void* const* d_in, const int* in_sizes, int n_in,
                              void* d_out, int out_size) {
    const float* emb = (const float*)d_in[0];
    const int*   lbl = (const int*)d_in[1];   // jax int64 -> int32 (no x64)
    (void)in_sizes; (void)n_in; (void)out_size;

    cudaFuncSetAttribute(dist_kernel, cudaFuncAttributeMaxDynamicSharedMemorySize, SM_TOTAL);

    prep_kernel<<<BATCH / 8, 256>>>(emb);
    dist_kernel<<<GRID_G, NTHREADS, SM_TOTAL>>>(lbl);
    finalize_kernel<<<1, 1024>>>((float*)d_out);
}